// round 14
// baseline (speedup 1.0000x reference)
#include <cuda_runtime.h>
#include <math.h>

#define TS 32
#define NT 256
#define IN_DIM 40
#define IN_STR 44
#define TMP_STR 38   // even: 8B-aligned float2 rows
#define BLUR_STR 38  // even: 8B-aligned float2 rows
#define BLUR_DIM 36
#define GM_DIM 34
#define GM_STR 35

#define IN_CH   (IN_DIM * IN_STR)     // 1760
#define TMP_CH  (IN_DIM * TMP_STR)    // 1520
#define BLUR_CH (BLUR_DIM * BLUR_STR) // 1368 (<= 1760, aliases s_in)

__global__ __launch_bounds__(NT) void canny_fused_kernel(
    const float* __restrict__ img, float* __restrict__ out,
    int H, int W)
{
    __shared__ float s_pool[3 * IN_CH];    // s_in[3]; aliased by s_blur[3]
    __shared__ float s_tmpa[3 * TMP_CH];   // s_tmp[3]; tail aliased by s_gmag after stage C
    __shared__ int s_noff[8];
    float* const s_gmag = s_tmpa;          // alias: s_tmp dead after stage C (sync before D)

    const int tid = threadIdx.x;
    const int x0 = blockIdx.x * TS;
    const int y0 = blockIdx.y * TS;
    const int b  = blockIdx.z;

    // proven literals + pinned forms (R13 passed with these)
    const float G0 = 0.13533528f;   // exp(-2)
    const float G1 = 0.60653067f;   // exp(-0.5)

    if (tid < 8) {
        const int ddy[8] = {0, 1, 1, 1, 0, -1, -1, -1};
        const int ddx[8] = {1, 1, 0, -1, -1, -1, 0, 1};
        s_noff[tid] = ddy[tid] * GM_STR + ddx[tid];
    }

    // ---- fixed per-thread mappings (computed ONCE) ----
    const int rA0 = tid / 10, cA0 = (tid - rA0 * 10) * 4;
    const int uA1 = tid + NT;
    const int rA1 = uA1 / 10, cA1 = (uA1 - rA1 * 10) * 4;
    const int tB_r = tid / 6, tB_c0 = (tid - tB_r * 6) * 6;       // tid<240
    const int tC_rs = tid / 18, tC_cc = (tid - tC_rs * 18) * 2;   // tid<108: 6 rowsegs x 18 colpairs
    const int tC_r0 = tC_rs * 6;
    const int tD_ty = tid / GM_DIM, tD_c = tid - tD_ty * GM_DIM;  // tid<238
    const int r0   = tD_ty * 5;
    const int rend = (r0 + 5 < GM_DIM) ? (r0 + 5) : GM_DIM;

    const bool interior = (x0 >= 32) && (x0 <= 448) && (y0 >= 32) && (y0 <= 448);
    const float* base = img + ((size_t)b * 3) * H * W;
    const size_t HW = (size_t)H * W;

    float amag[5], agx[5], agy[5];

    // ================= stage A: load all 3 channels =================
    if (interior) {
        const float* g0 = base + (size_t)(y0 - 4) * W + (x0 - 4);
        #pragma unroll
        for (int c = 0; c < 3; ++c) {
            const float* gc = g0 + (size_t)c * HW;
            float* sc = s_pool + c * IN_CH;
            *(float4*)(&sc[rA0 * IN_STR + cA0]) = *(const float4*)(gc + (size_t)rA0 * W + cA0);
            if (tid < 144)
                *(float4*)(&sc[rA1 * IN_STR + cA1]) = *(const float4*)(gc + (size_t)rA1 * W + cA1);
        }
    } else {
        for (int c = 0; c < 3; ++c) {
            const float* gc = base + (size_t)c * HW;
            float* sc = s_pool + c * IN_CH;
            for (int i = tid; i < IN_DIM * IN_DIM; i += NT) {
                int r = i / IN_DIM, cc = i - r * IN_DIM;
                int gy = y0 - 4 + r, gx = x0 - 4 + cc;
                float v = 0.0f;
                if (gy >= 0 && gy < H && gx >= 0 && gx < W) v = gc[(size_t)gy * W + gx];
                sc[r * IN_STR + cc] = v;
            }
        }
    }
    __syncthreads();

    // ================= stage B: horizontal gaussian (float2 preload / store) =================
    if (tid < 240) {
        #pragma unroll
        for (int c = 0; c < 3; ++c) {
            const float* si = s_pool + c * IN_CH + tB_r * IN_STR;
            float* st = s_tmpa + c * TMP_CH + tB_r * TMP_STR;
            float w[10];
            #pragma unroll
            for (int h = 0; h < 5; ++h) {
                float2 l = *(const float2*)(&si[tB_c0 + 2 * h]);
                w[2 * h] = l.x; w[2 * h + 1] = l.y;
            }
            float o[6];
            #pragma unroll
            for (int j = 0; j < 6; ++j) {
                float f1 = __fadd_rn(w[j], w[j + 4]);
                float f2 = __fadd_rn(w[j + 1], w[j + 3]);
                o[j] = __fadd_rn(__fmaf_rn(G0, f1, __fmul_rn(G1, f2)), w[j + 2]);
            }
            #pragma unroll
            for (int h = 0; h < 3; ++h)
                *(float2*)(&st[tB_c0 + 2 * h]) = make_float2(o[2 * h], o[2 * h + 1]);
        }
    }
    __syncthreads();

    // ================= stage C: vertical gaussian (column-pair float2 window) =================
    if (tid < 108) {
        #pragma unroll
        for (int c = 0; c < 3; ++c) {
            const float* st = s_tmpa + c * TMP_CH;
            float* sb = s_pool + c * BLUR_CH;
            int cc = tC_cc;
            float2 W0 = *(const float2*)(&st[(tC_r0 + 0) * TMP_STR + cc]);
            float2 W1 = *(const float2*)(&st[(tC_r0 + 1) * TMP_STR + cc]);
            float2 W2 = *(const float2*)(&st[(tC_r0 + 2) * TMP_STR + cc]);
            float2 W3 = *(const float2*)(&st[(tC_r0 + 3) * TMP_STR + cc]);
            float2 W4 = *(const float2*)(&st[(tC_r0 + 4) * TMP_STR + cc]);
            if (interior) {
                #pragma unroll
                for (int j = 0; j < 6; ++j) {
                    int r = tC_r0 + j;
                    float f1 = __fadd_rn(W0.x, W4.x);
                    float f2 = __fadd_rn(W1.x, W3.x);
                    float vx = __fadd_rn(__fmaf_rn(G0, f1, __fmul_rn(G1, f2)), W2.x);
                    float g1 = __fadd_rn(W0.y, W4.y);
                    float g2 = __fadd_rn(W1.y, W3.y);
                    float vy = __fadd_rn(__fmaf_rn(G0, g1, __fmul_rn(G1, g2)), W2.y);
                    *(float2*)(&sb[r * BLUR_STR + cc]) = make_float2(vx, vy);
                    if (j < 5) {
                        W0 = W1; W1 = W2; W2 = W3; W3 = W4;
                        W4 = *(const float2*)(&st[(r + 5) * TMP_STR + cc]);
                    }
                }
            } else {
                #pragma unroll
                for (int j = 0; j < 6; ++j) {
                    int r = tC_r0 + j;
                    int gy = y0 - 2 + r;
                    int gxa_ = x0 - 2 + cc, gxb_ = gxa_ + 1;
                    float vx = 0.0f, vy = 0.0f;
                    if (gy >= 0 && gy < H) {
                        if (gxa_ >= 0 && gxa_ < W) {
                            float f1 = __fadd_rn(W0.x, W4.x);
                            float f2 = __fadd_rn(W1.x, W3.x);
                            vx = __fadd_rn(__fmaf_rn(G0, f1, __fmul_rn(G1, f2)), W2.x);
                        }
                        if (gxb_ >= 0 && gxb_ < W) {
                            float g1 = __fadd_rn(W0.y, W4.y);
                            float g2 = __fadd_rn(W1.y, W3.y);
                            vy = __fadd_rn(__fmaf_rn(G0, g1, __fmul_rn(G1, g2)), W2.y);
                        }
                    }
                    *(float2*)(&sb[r * BLUR_STR + cc]) = make_float2(vx, vy);
                    if (j < 5) {
                        W0 = W1; W1 = W2; W2 = W3; W3 = W4;
                        W4 = *(const float2*)(&st[(r + 5) * TMP_STR + cc]);
                    }
                }
            }
        }
    }
    __syncthreads();

    // ================= stage D: sobel + |grad| (scalar rolling 3x3, R13 text) =================
    if (tid < 238) {
        int cc = tD_c;
        if (interior) {
            #pragma unroll
            for (int c = 0; c < 3; ++c) {
                const float* sb = s_pool + c * BLUR_CH;
                float t0 = sb[r0 * BLUR_STR + cc],       t1 = sb[r0 * BLUR_STR + cc + 1],       t2 = sb[r0 * BLUR_STR + cc + 2];
                float m0 = sb[(r0 + 1) * BLUR_STR + cc], m1 = sb[(r0 + 1) * BLUR_STR + cc + 1], m2 = sb[(r0 + 1) * BLUR_STR + cc + 2];
                #pragma unroll
                for (int k = 0; k < 5; ++k) {
                    int r = r0 + k;
                    if (r < rend) {
                        float b0 = sb[(r + 2) * BLUR_STR + cc], b1 = sb[(r + 2) * BLUR_STR + cc + 1], b2 = sb[(r + 2) * BLUR_STR + cc + 2];
                        float d1 = __fadd_rn(t0, -t2);
                        float d2 = __fadd_rn(m0, -m2);
                        float d3 = __fadd_rn(b0, -b2);
                        float gxv = __fadd_rn(__fmaf_rn(2.0f, d2, d1), d3);
                        float ta = __fadd_rn(__fmaf_rn(2.0f, t1, t0), t2);
                        float tb = __fadd_rn(__fmaf_rn(2.0f, b1, b0), b2);
                        float gyv = __fadd_rn(ta, -tb);
                        float mag = sqrtf(__fmaf_rn(gxv, gxv, __fmul_rn(gyv, gyv)));
                        if (c == 0) { amag[k] = mag;  agx[k] = gxv;  agy[k] = gyv; }
                        else {
                            amag[k] = __fadd_rn(amag[k], mag);
                            agx[k]  = __fadd_rn(agx[k], gxv);
                            agy[k]  = __fadd_rn(agy[k], gyv);
                        }
                        t0 = m0; t1 = m1; t2 = m2;
                        m0 = b0; m1 = b1; m2 = b2;
                    }
                }
            }
        } else {
            #pragma unroll
            for (int c = 0; c < 3; ++c) {
                const float* sb = s_pool + c * BLUR_CH;
                float t0 = sb[r0 * BLUR_STR + cc],       t1 = sb[r0 * BLUR_STR + cc + 1],       t2 = sb[r0 * BLUR_STR + cc + 2];
                float m0 = sb[(r0 + 1) * BLUR_STR + cc], m1 = sb[(r0 + 1) * BLUR_STR + cc + 1], m2 = sb[(r0 + 1) * BLUR_STR + cc + 2];
                #pragma unroll
                for (int k = 0; k < 5; ++k) {
                    int r = r0 + k;
                    if (r < rend) {
                        float b0 = sb[(r + 2) * BLUR_STR + cc], b1 = sb[(r + 2) * BLUR_STR + cc + 1], b2 = sb[(r + 2) * BLUR_STR + cc + 2];
                        int gyp = y0 - 1 + r, gxp = x0 - 1 + cc;
                        float mag = 0.0f, gxv = 0.0f, gyv = 0.0f;
                        if (gyp >= 0 && gyp < H && gxp >= 0 && gxp < W) {
                            float d1 = __fadd_rn(t0, -t2);
                            float d2 = __fadd_rn(m0, -m2);
                            float d3 = __fadd_rn(b0, -b2);
                            gxv = __fadd_rn(__fmaf_rn(2.0f, d2, d1), d3);
                            float ta = __fadd_rn(__fmaf_rn(2.0f, t1, t0), t2);
                            float tb = __fadd_rn(__fmaf_rn(2.0f, b1, b0), b2);
                            gyv = __fadd_rn(ta, -tb);
                            mag = sqrtf(__fmaf_rn(gxv, gxv, __fmul_rn(gyv, gyv)));
                        }
                        if (c == 0) { amag[k] = mag;  agx[k] = gxv;  agy[k] = gyv; }
                        else {
                            amag[k] = __fadd_rn(amag[k], mag);
                            agx[k]  = __fadd_rn(agx[k], gxv);
                            agy[k]  = __fadd_rn(agy[k], gyv);
                        }
                        t0 = m0; t1 = m1; t2 = m2;
                        m0 = b0; m1 = b1; m2 = b2;
                    }
                }
            }
        }
        // write summed grad-mag for neighbor gathers (s_gmag aliases s_tmpa; s_tmp dead)
        #pragma unroll
        for (int k = 0; k < 5; ++k) {
            int r = r0 + k;
            if (r < rend) s_gmag[r * GM_STR + cc] = amag[k];
        }
    }
    __syncthreads();

    // ================= NMS + threshold (pinned, R13 text) =================
    const float RAD2DEG = 180.0f / 3.14159f;  // matches reference literal
    if (tid < 238 && tD_c >= 1 && tD_c <= TS) {
        int cc = tD_c;
        #pragma unroll
        for (int k = 0; k < 5; ++k) {
            int r = r0 + k;
            if (r < rend && r >= 1 && r <= TS) {
                float gm = amag[k];
                float ang = __fmaf_rn(atan2f(agy[k], agx[k]), RAD2DEG, 180.0f);
                int q = (int)rintf(__fdiv_rn(ang, 45.0f));   // half-to-even like jnp.round
                int ip = q & 7;
                int in_ = (q + 4) & 7;
                int ci = r * GM_STR + cc;
                float pos = __fadd_rn(gm, -s_gmag[ci + s_noff[ip]]);
                float neg = __fadd_rn(gm, -s_gmag[ci + s_noff[in_]]);
                float thin = (fminf(pos, neg) > 0.0f) ? gm : 0.0f;
                float res = (thin < 10.0f) ? 0.0f : thin;
                out[((size_t)b * H + (y0 + r - 1)) * W + (x0 + cc - 1)] = res;
            }
        }
    }
}

extern "C" void kernel_launch(void* const* d_in, const int* in_sizes, int n_in,
                              void* d_out, int out_size)
{
    const float* img = (const float*)d_in[0];
    float* out = (float*)d_out;
    const int H = 512, W = 512;
    int B = in_sizes[0] / (3 * H * W);   // 16
    dim3 grid(W / TS, H / TS, B);
    canny_fused_kernel<<<grid, NT>>>(img, out, H, W);
}

// round 15
// speedup vs baseline: 1.1015x; 1.1015x over previous
#include <cuda_runtime.h>
#include <math.h>

#define TS 32
#define NT 256
#define IN_DIM 40
#define IN_STR 44
#define TMP_STR 37
#define BLUR_STR 37
#define BLUR_DIM 36
#define GM_DIM 34
#define GM_STR 35

#define IN_CH   (IN_DIM * IN_STR)     // 1760
#define TMP_CH  (IN_DIM * TMP_STR)    // 1480
#define BLUR_CH (BLUR_DIM * BLUR_STR) // 1332

__global__ __launch_bounds__(NT) void canny_fused_kernel(
    const float* __restrict__ img, float* __restrict__ out,
    int H, int W)
{
    __shared__ float s_pool[3 * IN_CH];    // s_in[3]; aliased by s_blur[3] (3*1332 < 3*1760)
    __shared__ float s_tmpa[3 * TMP_CH];
    __shared__ float s_gmag[GM_DIM * GM_STR];
    __shared__ int s_noff[8];

    const int tid = threadIdx.x;
    const int x0 = blockIdx.x * TS;
    const int y0 = blockIdx.y * TS;
    const int b  = blockIdx.z;

    // proven literals + pinned forms (R13 passed with these)
    const float G0 = 0.13533528f;   // exp(-2)
    const float G1 = 0.60653067f;   // exp(-0.5)

    if (tid < 8) {
        const int ddy[8] = {0, 1, 1, 1, 0, -1, -1, -1};
        const int ddx[8] = {1, 1, 0, -1, -1, -1, 0, 1};
        s_noff[tid] = ddy[tid] * GM_STR + ddx[tid];
    }

    // ---- fixed per-thread mappings (computed ONCE) ----
    const int rA0 = tid / 10, cA0 = (tid - rA0 * 10) * 4;
    const int uA1 = tid + NT;
    const int rA1 = uA1 / 10, cA1 = (uA1 - rA1 * 10) * 4;
    const int tB_r = tid / 6, tB_c0 = (tid - tB_r * 6) * 6;
    const int tC_rs = tid / 36, tC_c = tid - tC_rs * 36;
    const int tC_r0 = tC_rs * 6;
    const int tD_ty = tid / GM_DIM, tD_c = tid - tD_ty * GM_DIM;
    const int r0   = tD_ty * 5;
    const int rend = (r0 + 5 < GM_DIM) ? (r0 + 5) : GM_DIM;

    const bool interior = (x0 >= 32) && (x0 <= 448) && (y0 >= 32) && (y0 <= 448);
    const float* base = img + ((size_t)b * 3) * H * W;
    const size_t HW = (size_t)H * W;

    float amag[5], agx[5], agy[5];

    // ================= stage A: load all 3 channels =================
    if (interior) {
        const float* g0 = base + (size_t)(y0 - 4) * W + (x0 - 4);
        #pragma unroll
        for (int c = 0; c < 3; ++c) {
            const float* gc = g0 + (size_t)c * HW;
            float* sc = s_pool + c * IN_CH;
            *(float4*)(&sc[rA0 * IN_STR + cA0]) = *(const float4*)(gc + (size_t)rA0 * W + cA0);
            if (tid < 144)
                *(float4*)(&sc[rA1 * IN_STR + cA1]) = *(const float4*)(gc + (size_t)rA1 * W + cA1);
        }
    } else {
        for (int c = 0; c < 3; ++c) {
            const float* gc = base + (size_t)c * HW;
            float* sc = s_pool + c * IN_CH;
            for (int i = tid; i < IN_DIM * IN_DIM; i += NT) {
                int r = i / IN_DIM, cc = i - r * IN_DIM;
                int gy = y0 - 4 + r, gx = x0 - 4 + cc;
                float v = 0.0f;
                if (gy >= 0 && gy < H && gx >= 0 && gx < W) v = gc[(size_t)gy * W + gx];
                sc[r * IN_STR + cc] = v;
            }
        }
    }
    __syncthreads();

    // ================= stage B: horizontal gaussian (rolling window) =================
    if (tid < 240) {
        #pragma unroll
        for (int c = 0; c < 3; ++c) {
            const float* si = s_pool + c * IN_CH + tB_r * IN_STR;
            float* st = s_tmpa + c * TMP_CH + tB_r * TMP_STR;
            float w0 = si[tB_c0],     w1 = si[tB_c0 + 1], w2 = si[tB_c0 + 2];
            float w3 = si[tB_c0 + 3], w4 = si[tB_c0 + 4];
            #pragma unroll
            for (int j = 0; j < 6; ++j) {
                int cc = tB_c0 + j;
                float f1 = __fadd_rn(w0, w4);
                float f2 = __fadd_rn(w1, w3);
                st[cc] = __fadd_rn(__fmaf_rn(G0, f1, __fmul_rn(G1, f2)), w2);
                if (j < 5) {
                    float wn = si[cc + 5];
                    w0 = w1; w1 = w2; w2 = w3; w3 = w4; w4 = wn;
                }
            }
        }
    }
    __syncthreads();

    // ================= stage C: vertical gaussian (rolling window) =================
    if (tid < 216) {
        if (interior) {
            #pragma unroll
            for (int c = 0; c < 3; ++c) {
                const float* st = s_tmpa + c * TMP_CH;
                float* sb = s_pool + c * BLUR_CH;
                int cc = tC_c;
                float w0 = st[(tC_r0 + 0) * TMP_STR + cc], w1 = st[(tC_r0 + 1) * TMP_STR + cc];
                float w2 = st[(tC_r0 + 2) * TMP_STR + cc], w3 = st[(tC_r0 + 3) * TMP_STR + cc];
                float w4 = st[(tC_r0 + 4) * TMP_STR + cc];
                #pragma unroll
                for (int j = 0; j < 6; ++j) {
                    int r = tC_r0 + j;
                    float f1 = __fadd_rn(w0, w4);
                    float f2 = __fadd_rn(w1, w3);
                    sb[r * BLUR_STR + cc] = __fadd_rn(__fmaf_rn(G0, f1, __fmul_rn(G1, f2)), w2);
                    if (j < 5) {
                        float wn = st[(r + 5) * TMP_STR + cc];
                        w0 = w1; w1 = w2; w2 = w3; w3 = w4; w4 = wn;
                    }
                }
            }
        } else {
            #pragma unroll
            for (int c = 0; c < 3; ++c) {
                const float* st = s_tmpa + c * TMP_CH;
                float* sb = s_pool + c * BLUR_CH;
                int cc = tC_c;
                float w0 = st[(tC_r0 + 0) * TMP_STR + cc], w1 = st[(tC_r0 + 1) * TMP_STR + cc];
                float w2 = st[(tC_r0 + 2) * TMP_STR + cc], w3 = st[(tC_r0 + 3) * TMP_STR + cc];
                float w4 = st[(tC_r0 + 4) * TMP_STR + cc];
                #pragma unroll
                for (int j = 0; j < 6; ++j) {
                    int r = tC_r0 + j;
                    int gy = y0 - 2 + r, gx = x0 - 2 + cc;
                    float v = 0.0f;
                    if (gy >= 0 && gy < H && gx >= 0 && gx < W) {
                        float f1 = __fadd_rn(w0, w4);
                        float f2 = __fadd_rn(w1, w3);
                        v = __fadd_rn(__fmaf_rn(G0, f1, __fmul_rn(G1, f2)), w2);
                    }
                    sb[r * BLUR_STR + cc] = v;
                    if (j < 5) {
                        float wn = st[(r + 5) * TMP_STR + cc];
                        w0 = w1; w1 = w2; w2 = w3; w3 = w4; w4 = wn;
                    }
                }
            }
        }
    }
    __syncthreads();

    // ================= stage D: sobel + |grad| (rolling 3x3), channels inner =================
    if (tid < 238) {
        int cc = tD_c;
        if (interior) {
            #pragma unroll
            for (int c = 0; c < 3; ++c) {
                const float* sb = s_pool + c * BLUR_CH;
                float t0 = sb[r0 * BLUR_STR + cc],       t1 = sb[r0 * BLUR_STR + cc + 1],       t2 = sb[r0 * BLUR_STR + cc + 2];
                float m0 = sb[(r0 + 1) * BLUR_STR + cc], m1 = sb[(r0 + 1) * BLUR_STR + cc + 1], m2 = sb[(r0 + 1) * BLUR_STR + cc + 2];
                #pragma unroll
                for (int k = 0; k < 5; ++k) {
                    int r = r0 + k;
                    if (r < rend) {
                        float b0 = sb[(r + 2) * BLUR_STR + cc], b1 = sb[(r + 2) * BLUR_STR + cc + 1], b2 = sb[(r + 2) * BLUR_STR + cc + 2];
                        float d1 = __fadd_rn(t0, -t2);
                        float d2 = __fadd_rn(m0, -m2);
                        float d3 = __fadd_rn(b0, -b2);
                        float gxv = __fadd_rn(__fmaf_rn(2.0f, d2, d1), d3);
                        float ta = __fadd_rn(__fmaf_rn(2.0f, t1, t0), t2);
                        float tb = __fadd_rn(__fmaf_rn(2.0f, b1, b0), b2);
                        float gyv = __fadd_rn(ta, -tb);
                        float mag = sqrtf(__fmaf_rn(gxv, gxv, __fmul_rn(gyv, gyv)));
                        if (c == 0) { amag[k] = mag;  agx[k] = gxv;  agy[k] = gyv; }
                        else {
                            amag[k] = __fadd_rn(amag[k], mag);
                            agx[k]  = __fadd_rn(agx[k], gxv);
                            agy[k]  = __fadd_rn(agy[k], gyv);
                        }
                        t0 = m0; t1 = m1; t2 = m2;
                        m0 = b0; m1 = b1; m2 = b2;
                    }
                }
            }
        } else {
            #pragma unroll
            for (int c = 0; c < 3; ++c) {
                const float* sb = s_pool + c * BLUR_CH;
                float t0 = sb[r0 * BLUR_STR + cc],       t1 = sb[r0 * BLUR_STR + cc + 1],       t2 = sb[r0 * BLUR_STR + cc + 2];
                float m0 = sb[(r0 + 1) * BLUR_STR + cc], m1 = sb[(r0 + 1) * BLUR_STR + cc + 1], m2 = sb[(r0 + 1) * BLUR_STR + cc + 2];
                #pragma unroll
                for (int k = 0; k < 5; ++k) {
                    int r = r0 + k;
                    if (r < rend) {
                        float b0 = sb[(r + 2) * BLUR_STR + cc], b1 = sb[(r + 2) * BLUR_STR + cc + 1], b2 = sb[(r + 2) * BLUR_STR + cc + 2];
                        int gyp = y0 - 1 + r, gxp = x0 - 1 + cc;
                        float mag = 0.0f, gxv = 0.0f, gyv = 0.0f;
                        if (gyp >= 0 && gyp < H && gxp >= 0 && gxp < W) {
                            float d1 = __fadd_rn(t0, -t2);
                            float d2 = __fadd_rn(m0, -m2);
                            float d3 = __fadd_rn(b0, -b2);
                            gxv = __fadd_rn(__fmaf_rn(2.0f, d2, d1), d3);
                            float ta = __fadd_rn(__fmaf_rn(2.0f, t1, t0), t2);
                            float tb = __fadd_rn(__fmaf_rn(2.0f, b1, b0), b2);
                            gyv = __fadd_rn(ta, -tb);
                            mag = sqrtf(__fmaf_rn(gxv, gxv, __fmul_rn(gyv, gyv)));
                        }
                        if (c == 0) { amag[k] = mag;  agx[k] = gxv;  agy[k] = gyv; }
                        else {
                            amag[k] = __fadd_rn(amag[k], mag);
                            agx[k]  = __fadd_rn(agx[k], gxv);
                            agy[k]  = __fadd_rn(agy[k], gyv);
                        }
                        t0 = m0; t1 = m1; t2 = m2;
                        m0 = b0; m1 = b1; m2 = b2;
                    }
                }
            }
        }
        // write summed grad-mag for neighbor gathers
        #pragma unroll
        for (int k = 0; k < 5; ++k) {
            int r = r0 + k;
            if (r < rend) s_gmag[r * GM_STR + cc] = amag[k];
        }
    }
    __syncthreads();

    // ================= NMS + threshold: octant classification (no atan2) =================
    // axis a = q&3 where q = rintf((atan2f*R+180)/45); {q&7,(q+4)&7} == {a, a+4} and
    // fminf(pos,neg) is symmetric, so only the axis matters.
    // Boundaries at (k+0.5)*45*3.14159/180 true radians:
    //   t1 = tan(0.392698750) = 0.41421320, t2 = tan(1.178096250) = 2.41420674
    const float T1 = 0.41421320f;
    const float T2 = 2.41420674f;
    if (tid < 238 && tD_c >= 1 && tD_c <= TS) {
        int cc = tD_c;
        #pragma unroll
        for (int k = 0; k < 5; ++k) {
            int r = r0 + k;
            if (r < rend && r >= 1 && r <= TS) {
                float gm = amag[k];
                float X = agx[k], Y = agy[k];
                float ax = fabsf(X), ay = fabsf(Y);
                int a;
                if (ay <= __fmul_rn(T1, ax))      a = 0;
                else if (ay >= __fmul_rn(T2, ax)) a = 2;
                else a = ((__float_as_int(X) ^ __float_as_int(Y)) >= 0) ? 1 : 3;
                int ci = r * GM_STR + cc;
                float pos = __fadd_rn(gm, -s_gmag[ci + s_noff[a]]);
                float neg = __fadd_rn(gm, -s_gmag[ci + s_noff[a + 4]]);
                float thin = (fminf(pos, neg) > 0.0f) ? gm : 0.0f;
                float res = (thin < 10.0f) ? 0.0f : thin;
                out[((size_t)b * H + (y0 + r - 1)) * W + (x0 + cc - 1)] = res;
            }
        }
    }
}

extern "C" void kernel_launch(void* const* d_in, const int* in_sizes, int n_in,
                              void* d_out, int out_size)
{
    const float* img = (const float*)d_in[0];
    float* out = (float*)d_out;
    const int H = 512, W = 512;
    int B = in_sizes[0] / (3 * H * W);   // 16
    dim3 grid(W / TS, H / TS, B);
    canny_fused_kernel<<<grid, NT>>>(img, out, H, W);
}